// round 8
// baseline (speedup 1.0000x reference)
#include <cuda_runtime.h>
#include <cuda_fp16.h>
#include <cstdint>

// CapsuleLayer dynamic routing, B=512, R=640, C=10, O=16, I=8, 3 iters.
// Kernel 1: u_hat einsum -> fp16 scratch. 160-thr blocks, grid r x batch/4,
//           5 CTAs/SM; co-pair packed fma.rn.f32x2, W in regs.
// Kernel 2: routing, 4-CTA cluster per batch (160 r's, 67.6KB smem each),
//           3 CTAs/SM; per-iter s_j partials exchanged via DSMEM 4-way.

#define BB 512
#define RR 640
#define RQ  160          // r's per route CTA
#define CC 10
#define OO 16
#define COO 160
#define II 8

__device__ __half g_uhat[(size_t)BB * RR * COO];

typedef unsigned long long ull;
__device__ __forceinline__ ull pack2(float lo, float hi) {
    ull r; asm("mov.b64 %0, {%1, %2};" : "=l"(r) : "f"(lo), "f"(hi)); return r;
}
__device__ __forceinline__ void unpack2(ull v, float& lo, float& hi) {
    asm("mov.b64 {%0, %1}, %2;" : "=f"(lo), "=f"(hi) : "l"(v));
}
__device__ __forceinline__ ull fma2(ull a, ull b, ull c) {
    ull d; asm("fma.rn.f32x2 %0, %1, %2, %3;" : "=l"(d) : "l"(a), "l"(b), "l"(c)); return d;
}
__device__ __forceinline__ ull add2(ull a, ull b) {
    ull d; asm("add.rn.f32x2 %0, %1, %2;" : "=l"(d) : "l"(a), "l"(b)); return d;
}
__device__ __forceinline__ ull h2f2(unsigned int h) {
    __half2 hh = *reinterpret_cast<__half2*>(&h);
    float2 f = __half22float2(hh);
    ull u; memcpy(&u, &f, 8); return u;
}
__device__ __forceinline__ uint32_t smem_u32(const void* p) {
    uint32_t a;
    asm("{ .reg .u64 t; cvta.to.shared.u64 t, %1; cvt.u32.u64 %0, t; }" : "=r"(a) : "l"(p));
    return a;
}
__device__ __forceinline__ void dsmem_st_f32(uint32_t laddr, uint32_t rank, float v) {
    uint32_t raddr;
    asm volatile("mapa.shared::cluster.u32 %0, %1, %2;" : "=r"(raddr) : "r"(laddr), "r"(rank));
    asm volatile("st.shared::cluster.f32 [%0], %1;" :: "r"(raddr), "f"(v) : "memory");
}
#define CLUSTER_SYNC() do { \
    asm volatile("barrier.cluster.arrive.aligned;" ::: "memory"); \
    asm volatile("barrier.cluster.wait.aligned;"   ::: "memory"); } while (0)

// =====================================================================
// Kernel 1: grid=2560 (r = bid>>2, bq = bid&3 -> 128 batches), 160 thr,
// 5 CTAs/SM. thread: cg=t%40 -> co quad; pl=t/40 in [0,4) -> 32 batches.
// Per batch: 4 LDS.128 (dup'd x, broadcast), 16 FFMA2, 1 STG.64.
// =====================================================================
__global__ __launch_bounds__(160, 5) void uhat_kernel(const float* __restrict__ x,
                                                      const float* __restrict__ W) {
    const int r  = blockIdx.x >> 2;
    const int bq = blockIdx.x & 3;          // batch quarter: [bq*128, bq*128+128)
    __shared__ float ws[COO * II];          // 5120B
    __shared__ ull   xs2[128 * II];         // 8192B: xs2[bl*8+i] = (x,x) dup
    const int tid = threadIdx.x;

    for (int idx = tid; idx < COO * II; idx += 160)
        ws[idx] = W[(size_t)r * (COO * II) + idx];
    for (int idx = tid; idx < 128 * 2; idx += 160) {
        int bl = idx >> 1, hf = idx & 1;
        float4 v = *(const float4*)(x + (size_t)(bq * 128 + bl) * (RR * II) + r * II + hf * 4);
        ull* dst = xs2 + bl * 8 + hf * 4;
        dst[0] = pack2(v.x, v.x); dst[1] = pack2(v.y, v.y);
        dst[2] = pack2(v.z, v.z); dst[3] = pack2(v.w, v.w);
    }
    __syncthreads();

    const int cg = tid % 40;                // co quad base = cg*4
    const int pl = tid / 40;                // 0..3

    ull wp0[8], wp1[8];                     // co-pair packed W: 32 regs
#pragma unroll
    for (int i = 0; i < 8; i++) {
        wp0[i] = pack2(ws[(cg * 4 + 0) * 8 + i], ws[(cg * 4 + 1) * 8 + i]);
        wp1[i] = pack2(ws[(cg * 4 + 2) * 8 + i], ws[(cg * 4 + 3) * 8 + i]);
    }

    __half* outp = g_uhat;
    for (int bl = pl; bl < 128; bl += 4) {
        const ulonglong2* xp = (const ulonglong2*)(xs2 + bl * 8);
        ulonglong2 q0 = xp[0], q1 = xp[1], q2 = xp[2], q3 = xp[3];
        ull a0 = 0ull, a1 = 0ull;
        a0 = fma2(q0.x, wp0[0], a0);  a1 = fma2(q0.x, wp1[0], a1);
        a0 = fma2(q0.y, wp0[1], a0);  a1 = fma2(q0.y, wp1[1], a1);
        a0 = fma2(q1.x, wp0[2], a0);  a1 = fma2(q1.x, wp1[2], a1);
        a0 = fma2(q1.y, wp0[3], a0);  a1 = fma2(q1.y, wp1[3], a1);
        a0 = fma2(q2.x, wp0[4], a0);  a1 = fma2(q2.x, wp1[4], a1);
        a0 = fma2(q2.y, wp0[5], a0);  a1 = fma2(q2.y, wp1[5], a1);
        a0 = fma2(q3.x, wp0[6], a0);  a1 = fma2(q3.x, wp1[6], a1);
        a0 = fma2(q3.y, wp0[7], a0);  a1 = fma2(q3.y, wp1[7], a1);
        float f0, f1, f2, f3;
        unpack2(a0, f0, f1);
        unpack2(a1, f2, f3);
        __half2 h01 = __floats2half2_rn(f0, f1);
        __half2 h23 = __floats2half2_rn(f2, f3);
        uint2 st; st.x = *(unsigned*)&h01; st.y = *(unsigned*)&h23;
        const int bb = bq * 128 + bl;
        *(uint2*)(outp + ((size_t)bb * RR + r) * COO + cg * 4) = st;
    }
}

// =====================================================================
// Kernel 2: routing, cluster(4) per batch. grid=2048, 320 thr, 67,584B smem,
// 3 CTAs/SM (launch_bounds cap 68 regs).
// SMEM per CTA:
//   [0,     51200) uh fp16 [r_local*160+co]   (160 r's)
//   [51200, 61440) UNION { redf f32[16][160] ; a_s/cij half[160*10] }
//   [61440, 62080) sv f32[160]
//   [62080, 67200) rbuf f32[2(par)][4(src rank)][160]
// Mappings: thread-per-r uses t<160 (b_ij in regs of t<160);
// (rg=t/20 in [0,16), cq=t%20=c*2+oh) sweeps: 10 r's each, uint4 per r.
// =====================================================================
#define SM_UNI   51200
#define SM_SV    61440
#define SM_RBUF  62080
#define SM_TOTAL 67584

__global__ __launch_bounds__(320, 3) __cluster_dims__(4, 1, 1)
void route_kernel(const float* __restrict__ bias, float* __restrict__ out) {
    extern __shared__ unsigned char sm[];
    __half* uh   = (__half*)(sm);
    float*  redf = (float*)(sm + SM_UNI);
    __half* a_s  = (__half*)(sm + SM_UNI);
    __half* cijh = (__half*)(sm + SM_UNI);
    float*  sv   = (float*)(sm + SM_SV);
    float*  rbuf = (float*)(sm + SM_RBUF);

    const int b       = blockIdx.x >> 2;
    const uint32_t rk = blockIdx.x & 3;       // ctarank in cluster
    const int t       = threadIdx.x;

    // ---- stage this CTA's quarter of u_hat[b] (50 KB fp16) ----
    {
        const uint4* src = (const uint4*)(g_uhat + ((size_t)b * RR + rk * RQ) * COO);
        uint4* dst = (uint4*)uh;
#pragma unroll
        for (int i = 0; i < 10; i++)
            dst[i * 320 + t] = src[i * 320 + t];
    }

    const float biasv = (t < COO) ? bias[t] : 0.f;

    float bij[CC];
#pragma unroll
    for (int c = 0; c < CC; c++) bij[c] = 0.f;

    const int rg   = t / 20;                  // 16 groups of 10 local r's
    const int cq   = t % 20;                  // c*2 + ohalf
    const int c_of = cq >> 1;
    const int oh   = cq & 1;
    const __half* uptr0 = uh + (rg * 10) * COO + cq * 8;
    const uint32_t rbuf_base = smem_u32(rbuf);

    __syncthreads();

    // ---- iteration-0 fast path: c_ij = 0.1 folded into reduce ----
    {
        ull s0 = 0ull, s1 = 0ull, s2 = 0ull, s3 = 0ull;
        const __half* p = uptr0;
#pragma unroll 5
        for (int rr = 0; rr < 10; rr++) {
            uint4 h = *(const uint4*)p; p += COO;
            s0 = add2(s0, h2f2(h.x)); s1 = add2(s1, h2f2(h.y));
            s2 = add2(s2, h2f2(h.z)); s3 = add2(s3, h2f2(h.w));
        }
        float f0, f1, f2, f3, f4, f5, f6, f7;
        unpack2(s0, f0, f1); unpack2(s1, f2, f3);
        unpack2(s2, f4, f5); unpack2(s3, f6, f7);
        float* rp = redf + rg * COO + cq * 8;
        *(float4*)(rp)     = make_float4(f0, f1, f2, f3);
        *(float4*)(rp + 4) = make_float4(f4, f5, f6, f7);
    }
    __syncthreads();

    for (int it = 0; it < 3; ++it) {
        const int par = it & 1;
        // ---- local reduce + DSMEM 4-way exchange ----
        if (t < COO) {
            float s_loc = 0.f;
#pragma unroll
            for (int g = 0; g < 16; g++) s_loc += redf[g * COO + t];
            const uint32_t la = rbuf_base + ((par * 4 + rk) * COO + t) * 4;
#pragma unroll
            for (uint32_t k = 0; k < 4; k++) dsmem_st_f32(la, k, s_loc);
        }
        CLUSTER_SYNC();
        // ---- total s + squash (identical on all 4 CTAs) ----
        if (t < COO) {
            const float* rb = rbuf + par * 4 * COO + t;
            float s = (rb[0] + rb[COO]) + (rb[2 * COO] + rb[3 * COO]);
            s = (it == 0) ? fmaf(s, 0.1f, biasv) : (s + biasv);
            float n2 = s * s;
            n2 += __shfl_xor_sync(0xffffffffu, n2, 1);
            n2 += __shfl_xor_sync(0xffffffffu, n2, 2);
            n2 += __shfl_xor_sync(0xffffffffu, n2, 4);
            n2 += __shfl_xor_sync(0xffffffffu, n2, 8);
            float scale = sqrtf(n2) / (1.0f + n2 + 1e-8f);
            float v = s * scale;
            sv[t] = v;
            if (it == 2 && rk == 0) out[(size_t)b * COO + t] = v;
        }
        if (it == 2) break;
        __syncthreads();

        // ---- a_ij = <u_hat, v>; writes a_s (over redf, consumed above) ----
        {
            const float4 lv0 = *(const float4*)(sv + cq * 8);
            const float4 lv1 = *(const float4*)(sv + cq * 8 + 4);
            const ull v0 = pack2(lv0.x, lv0.y), v1 = pack2(lv0.z, lv0.w);
            const ull v2 = pack2(lv1.x, lv1.y), v3 = pack2(lv1.z, lv1.w);
            const __half* p = uptr0;
#pragma unroll 5
            for (int rr = 0; rr < 10; rr++) {
                uint4 h = *(const uint4*)p; p += COO;
                ull pp = fma2(h2f2(h.x), v0, 0ull);
                pp = fma2(h2f2(h.y), v1, pp);
                pp = fma2(h2f2(h.z), v2, pp);
                pp = fma2(h2f2(h.w), v3, pp);
                float plo, phi; unpack2(pp, plo, phi);
                float ps = plo + phi;
                ps += __shfl_xor_sync(0xffffffffu, ps, 1);
                if (oh == 0) a_s[(rg * 10 + rr) * CC + c_of] = __float2half_rn(ps);
            }
        }
        __syncthreads();

        // ---- merged: b_ij += a_ij, softmax -> cijh (t<160, same indices) ----
        if (t < RQ) {
            const __half2* ar = (const __half2*)(a_s + t * CC);
            float2 f[5];
#pragma unroll
            for (int q = 0; q < 5; q++) f[q] = __half22float2(ar[q]);
#pragma unroll
            for (int q = 0; q < 5; q++) {
                bij[2 * q]     += f[q].x;
                bij[2 * q + 1] += f[q].y;
            }
            float e[CC]; float ssum = 0.f;
#pragma unroll
            for (int c = 0; c < CC; c++) { e[c] = __expf(bij[c]); ssum += e[c]; }
            float inv = __fdividef(1.0f, ssum);
            __half2* cw = (__half2*)(cijh + t * CC);
#pragma unroll
            for (int q = 0; q < 5; q++)
                cw[q] = __floats2half2_rn(e[2 * q] * inv, e[2 * q + 1] * inv);
        }
        __syncthreads();

        // ---- s_j partials: sum_r c_ij * u_hat -> redf (bar before overlay) ----
        {
            ull s0 = 0ull, s1 = 0ull, s2 = 0ull, s3 = 0ull;
            const __half* cp = cijh + (rg * 10) * CC + c_of;
            const __half* p = uptr0;
#pragma unroll 5
            for (int rr = 0; rr < 10; rr++) {
                uint4 h = *(const uint4*)p; p += COO;
                float cwv = __half2float(*cp); cp += CC;
                ull cwp = pack2(cwv, cwv);
                s0 = fma2(h2f2(h.x), cwp, s0);
                s1 = fma2(h2f2(h.y), cwp, s1);
                s2 = fma2(h2f2(h.z), cwp, s2);
                s3 = fma2(h2f2(h.w), cwp, s3);
            }
            __syncthreads();   // all cij reads done before redf overlay write
            float f0, f1, f2, f3, f4, f5, f6, f7;
            unpack2(s0, f0, f1); unpack2(s1, f2, f3);
            unpack2(s2, f4, f5); unpack2(s3, f6, f7);
            float* rp = redf + rg * COO + cq * 8;
            *(float4*)(rp)     = make_float4(f0, f1, f2, f3);
            *(float4*)(rp + 4) = make_float4(f4, f5, f6, f7);
        }
        __syncthreads();
    }
}

// =====================================================================
extern "C" void kernel_launch(void* const* d_in, const int* in_sizes, int n_in,
                              void* d_out, int out_size) {
    const float* x = nullptr;
    const float* W = nullptr;
    const float* bias = nullptr;
    for (int i = 0; i < n_in; i++) {
        if (in_sizes[i] == BB * RR * II)            x    = (const float*)d_in[i];
        else if (in_sizes[i] == RR * CC * OO * II)  W    = (const float*)d_in[i];
        else if (in_sizes[i] == CC * OO)            bias = (const float*)d_in[i];
    }

    cudaFuncSetAttribute(route_kernel, cudaFuncAttributeMaxDynamicSharedMemorySize,
                         SM_TOTAL);

    uhat_kernel<<<RR * 4, 160>>>(x, W);
    route_kernel<<<BB * 4, 320, SM_TOTAL>>>(bias, (float*)d_out);
}

// round 14
// speedup vs baseline: 1.0325x; 1.0325x over previous
#include <cuda_runtime.h>
#include <cuda_fp16.h>
#include <cstdint>

// CapsuleLayer dynamic routing, B=512, R=640, C=10, O=16, I=8, 3 iters.
// Kernel 1: u_hat einsum -> fp16 scratch (R7-proven shape).
// Kernel 2: routing, cluster(4) per batch, 160 r's/CTA. it0 sum fused into
//           staging; iterations do ONE fused sweep each (a + b-update +
//           softmax + s-accumulate, b_ij in sweep-lane registers).
// R9 fix: b_ij init condition is it==0 (first sweep), not it==1 — the first
//         sweep was adding stale register garbage into b_ij.

#define BB 512
#define RR 640
#define RQ  160          // r's per route CTA
#define CC 10
#define OO 16
#define COO 160
#define II 8

__device__ __half g_uhat[(size_t)BB * RR * COO];

typedef unsigned long long ull;
__device__ __forceinline__ ull pack2(float lo, float hi) {
    ull r; asm("mov.b64 %0, {%1, %2};" : "=l"(r) : "f"(lo), "f"(hi)); return r;
}
__device__ __forceinline__ void unpack2(ull v, float& lo, float& hi) {
    asm("mov.b64 {%0, %1}, %2;" : "=f"(lo), "=f"(hi) : "l"(v));
}
__device__ __forceinline__ ull fma2(ull a, ull b, ull c) {
    ull d; asm("fma.rn.f32x2 %0, %1, %2, %3;" : "=l"(d) : "l"(a), "l"(b), "l"(c)); return d;
}
__device__ __forceinline__ ull add2(ull a, ull b) {
    ull d; asm("add.rn.f32x2 %0, %1, %2;" : "=l"(d) : "l"(a), "l"(b)); return d;
}
__device__ __forceinline__ ull h2f2(unsigned int h) {
    __half2 hh = *reinterpret_cast<__half2*>(&h);
    float2 f = __half22float2(hh);
    ull u; memcpy(&u, &f, 8); return u;
}
__device__ __forceinline__ uint32_t smem_u32(const void* p) {
    uint32_t a;
    asm("{ .reg .u64 t; cvta.to.shared.u64 t, %1; cvt.u32.u64 %0, t; }" : "=r"(a) : "l"(p));
    return a;
}
__device__ __forceinline__ void dsmem_st_f32(uint32_t laddr, uint32_t rank, float v) {
    uint32_t raddr;
    asm volatile("mapa.shared::cluster.u32 %0, %1, %2;" : "=r"(raddr) : "r"(laddr), "r"(rank));
    asm volatile("st.shared::cluster.f32 [%0], %1;" :: "r"(raddr), "f"(v) : "memory");
}
#define CLUSTER_SYNC() do { \
    asm volatile("barrier.cluster.arrive.aligned;" ::: "memory"); \
    asm volatile("barrier.cluster.wait.aligned;"   ::: "memory"); } while (0)

// =====================================================================
// Kernel 1 (R7-proven): grid=640 (block per r), 320 threads, 2 CTAs/SM.
// thread: cg=t%40 -> co quad; pl=t/40 -> batch lane (step 8).
// =====================================================================
__global__ __launch_bounds__(320, 2) void uhat_kernel(const float* __restrict__ x,
                                                      const float* __restrict__ W) {
    const int r = blockIdx.x;
    __shared__ float ws[COO * II];          // 5120B
    __shared__ ull   xs2[BB * II];          // 32768B: xs2[b*8+i] = (x,x) dup
    const int tid = threadIdx.x;

    for (int idx = tid; idx < COO * II; idx += 320)
        ws[idx] = W[(size_t)r * (COO * II) + idx];
    for (int idx = tid; idx < BB * 2; idx += 320) {
        int bb = idx >> 1, hf = idx & 1;
        float4 v = *(const float4*)(x + (size_t)bb * (RR * II) + r * II + hf * 4);
        ull* dst = xs2 + bb * 8 + hf * 4;
        dst[0] = pack2(v.x, v.x); dst[1] = pack2(v.y, v.y);
        dst[2] = pack2(v.z, v.z); dst[3] = pack2(v.w, v.w);
    }
    __syncthreads();

    const int cg = tid % 40;                // co quad base = cg*4
    const int pl = tid / 40;                // 0..7

    ull wp0[8], wp1[8];                     // co-pair packed W: 32 regs
#pragma unroll
    for (int i = 0; i < 8; i++) {
        wp0[i] = pack2(ws[(cg * 4 + 0) * 8 + i], ws[(cg * 4 + 1) * 8 + i]);
        wp1[i] = pack2(ws[(cg * 4 + 2) * 8 + i], ws[(cg * 4 + 3) * 8 + i]);
    }

    __half* outp = g_uhat;
    for (int bb = pl; bb < BB; bb += 8) {
        const ulonglong2* xp = (const ulonglong2*)(xs2 + bb * 8);
        ulonglong2 q0 = xp[0], q1 = xp[1], q2 = xp[2], q3 = xp[3];
        ull a0 = 0ull, a1 = 0ull;
        a0 = fma2(q0.x, wp0[0], a0);  a1 = fma2(q0.x, wp1[0], a1);
        a0 = fma2(q0.y, wp0[1], a0);  a1 = fma2(q0.y, wp1[1], a1);
        a0 = fma2(q1.x, wp0[2], a0);  a1 = fma2(q1.x, wp1[2], a1);
        a0 = fma2(q1.y, wp0[3], a0);  a1 = fma2(q1.y, wp1[3], a1);
        a0 = fma2(q2.x, wp0[4], a0);  a1 = fma2(q2.x, wp1[4], a1);
        a0 = fma2(q2.y, wp0[5], a0);  a1 = fma2(q2.y, wp1[5], a1);
        a0 = fma2(q3.x, wp0[6], a0);  a1 = fma2(q3.x, wp1[6], a1);
        a0 = fma2(q3.y, wp0[7], a0);  a1 = fma2(q3.y, wp1[7], a1);
        float f0, f1, f2, f3;
        unpack2(a0, f0, f1);
        unpack2(a1, f2, f3);
        __half2 h01 = __floats2half2_rn(f0, f1);
        __half2 h23 = __floats2half2_rn(f2, f3);
        uint2 st; st.x = *(unsigned*)&h01; st.y = *(unsigned*)&h23;
        *(uint2*)(outp + ((size_t)bb * RR + r) * COO + cg * 4) = st;
    }
}

// =====================================================================
// Kernel 2: routing, cluster(4) per batch. grid=2048, 320 thr, 67,584B smem,
// 3 CTAs/SM.
// SMEM per CTA:
//   [0,     51200) uh fp16 [r_local*160+co]  (160 r's)
//   [51200, 61440) redf f32[16][160]  (it0: 16 staging rows; it1/2: 10 warp rows)
//   [61440, 62080) sv f32[160]
//   [62080, 67200) rbuf f32[2(par)][4(src rank)][160]
// Sweep mapping: warp w in [0,10) owns r = w*16+rr; lanes 0-19 own co-octets
// (idle lanes alias lane-12 -> smem broadcast); b_ij lives in sweep-lane regs.
// =====================================================================
#define SM_REDF  51200
#define SM_SV    61440
#define SM_RBUF  62080
#define SM_TOTAL 67584

__global__ __launch_bounds__(320, 3) __cluster_dims__(4, 1, 1)
void route_kernel(const float* __restrict__ bias, float* __restrict__ out) {
    extern __shared__ unsigned char sm[];
    __half* uh   = (__half*)(sm);
    float*  redf = (float*)(sm + SM_REDF);
    float*  sv   = (float*)(sm + SM_SV);
    float*  rbuf = (float*)(sm + SM_RBUF);

    const int b       = blockIdx.x >> 2;
    const uint32_t rk = blockIdx.x & 3;       // ctarank in cluster
    const int t       = threadIdx.x;
    const int l       = t & 31;
    const int w       = t >> 5;               // warp in [0,10)
    const int cq_eff  = (l < 20) ? l : (l - 12);
    const bool act    = (l < 20);

    // ---- stage u_hat quarter (50 KB) AND accumulate it-0 sum in flight ----
    // chunk idx i*320+t: co-octet = t%20 (constant over i), r = i*16 + t/20.
    {
        const uint4* src = (const uint4*)(g_uhat + ((size_t)b * RR + rk * RQ) * COO);
        uint4* dst = (uint4*)uh;
        ull s0 = 0ull, s1 = 0ull, s2 = 0ull, s3 = 0ull;
#pragma unroll
        for (int i = 0; i < 10; i++) {
            uint4 h = src[i * 320 + t];
            dst[i * 320 + t] = h;
            s0 = add2(s0, h2f2(h.x)); s1 = add2(s1, h2f2(h.y));
            s2 = add2(s2, h2f2(h.z)); s3 = add2(s3, h2f2(h.w));
        }
        float f0, f1, f2, f3, f4, f5, f6, f7;
        unpack2(s0, f0, f1); unpack2(s1, f2, f3);
        unpack2(s2, f4, f5); unpack2(s3, f6, f7);
        float* rp = redf + (t / 20) * COO + (t % 20) * 8;
        *(float4*)(rp)     = make_float4(f0, f1, f2, f3);
        *(float4*)(rp + 4) = make_float4(f4, f5, f6, f7);
    }

    const float biasv = (t < COO) ? bias[t] : 0.f;
    const uint32_t rbuf_base = smem_u32(rbuf);
    const __half* uptr0 = uh + (w * 16) * COO + cq_eff * 8;

    float bcap[16];                           // b_ij per local r (sweep lanes)

    __syncthreads();

    for (int it = 0; it < 3; ++it) {
        const int par = it & 1;
        const int nrows = (it == 0) ? 16 : 10;
        // ---- local reduce + DSMEM 4-way exchange ----
        if (t < COO) {
            float s_loc = 0.f;
            for (int g = 0; g < nrows; g++) s_loc += redf[g * COO + t];
            const uint32_t la = rbuf_base + ((par * 4 + rk) * COO + t) * 4;
#pragma unroll
            for (uint32_t k = 0; k < 4; k++) dsmem_st_f32(la, k, s_loc);
        }
        CLUSTER_SYNC();
        // ---- total s + squash (identical on all 4 CTAs) ----
        if (t < COO) {
            const float* rb = rbuf + par * 4 * COO + t;
            float s = (rb[0] + rb[COO]) + (rb[2 * COO] + rb[3 * COO]);
            s = (it == 0) ? fmaf(s, 0.1f, biasv) : (s + biasv);
            float n2 = s * s;
            n2 += __shfl_xor_sync(0xffffffffu, n2, 1);
            n2 += __shfl_xor_sync(0xffffffffu, n2, 2);
            n2 += __shfl_xor_sync(0xffffffffu, n2, 4);
            n2 += __shfl_xor_sync(0xffffffffu, n2, 8);
            float scale = sqrtf(n2) / (1.0f + n2 + 1e-8f);
            float v = s * scale;
            sv[t] = v;
            if (it == 2 && rk == 0) out[(size_t)b * COO + t] = v;
        }
        if (it == 2) break;
        __syncthreads();

        // ---- FUSED sweep: a = <u,v>; b += a; softmax; s += c*u ----
        {
            const float4 va = *(const float4*)(sv + cq_eff * 8);
            const float4 vb = *(const float4*)(sv + cq_eff * 8 + 4);
            const ull v0 = pack2(va.x, va.y), v1 = pack2(va.z, va.w);
            const ull v2 = pack2(vb.x, vb.y), v3 = pack2(vb.z, vb.w);
            ull s0 = 0ull, s1 = 0ull, s2 = 0ull, s3 = 0ull;
            const __half* p = uptr0;
#pragma unroll
            for (int rr = 0; rr < 16; rr++) {
                uint4 h = *(const uint4*)p; p += COO;
                ull h0 = h2f2(h.x), h1 = h2f2(h.y), h2 = h2f2(h.z), h3 = h2f2(h.w);
                // agreement a_rc (full 16-o dot via pair shfl)
                ull pp = fma2(h0, v0, 0ull);
                pp = fma2(h1, v1, pp);
                pp = fma2(h2, v2, pp);
                pp = fma2(h3, v3, pp);
                float plo, phi; unpack2(pp, plo, phi);
                float ps = plo + phi;
                ps += __shfl_xor_sync(0xffffffffu, ps, 1);
                // b update (registers; both lanes of c-pair hold it).
                // First sweep happens at it==0: initialize, don't accumulate.
                float bnew = (it == 0) ? ps : (bcap[rr] + ps);
                bcap[rr] = bnew;
                // softmax over c: warp sum of exp (pairs double-count -> /2)
                float e = act ? __expf(bnew) : 0.f;
                float S = e;
                S += __shfl_xor_sync(0xffffffffu, S, 1);
                S += __shfl_xor_sync(0xffffffffu, S, 2);
                S += __shfl_xor_sync(0xffffffffu, S, 4);
                S += __shfl_xor_sync(0xffffffffu, S, 8);
                S += __shfl_xor_sync(0xffffffffu, S, 16);
                float cw = e * __fdividef(2.0f, S);
                // s-accumulate reusing loaded h regs
                ull cwp = pack2(cw, cw);
                s0 = fma2(h0, cwp, s0);
                s1 = fma2(h1, cwp, s1);
                s2 = fma2(h2, cwp, s2);
                s3 = fma2(h3, cwp, s3);
            }
            if (act) {
                float f0, f1, f2, f3, f4, f5, f6, f7;
                unpack2(s0, f0, f1); unpack2(s1, f2, f3);
                unpack2(s2, f4, f5); unpack2(s3, f6, f7);
                float* rp = redf + w * COO + cq_eff * 8;
                *(float4*)(rp)     = make_float4(f0, f1, f2, f3);
                *(float4*)(rp + 4) = make_float4(f4, f5, f6, f7);
            }
        }
        __syncthreads();
    }
}

// =====================================================================
extern "C" void kernel_launch(void* const* d_in, const int* in_sizes, int n_in,
                              void* d_out, int out_size) {
    const float* x = nullptr;
    const float* W = nullptr;
    const float* bias = nullptr;
    for (int i = 0; i < n_in; i++) {
        if (in_sizes[i] == BB * RR * II)            x    = (const float*)d_in[i];
        else if (in_sizes[i] == RR * CC * OO * II)  W    = (const float*)d_in[i];
        else if (in_sizes[i] == CC * OO)            bias = (const float*)d_in[i];
    }

    cudaFuncSetAttribute(route_kernel, cudaFuncAttributeMaxDynamicSharedMemorySize,
                         SM_TOTAL);

    uhat_kernel<<<RR, 320>>>(x, W);
    route_kernel<<<BB * 4, 320, SM_TOTAL>>>(bias, (float*)d_out);
}

// round 16
// speedup vs baseline: 1.1321x; 1.0965x over previous
#include <cuda_runtime.h>
#include <cuda_fp16.h>
#include <cstdint>

// CapsuleLayer dynamic routing, B=512, R=640, C=10, O=16, I=8, 3 iters.
// Kernel 1: u_hat einsum -> fp16 scratch. Grid r x batch-half (1280 blocks)
//           to cut wave quantization; non-dup x in smem (2 LDS.128/batch),
//           pair-dup via ALU movs; co-pair packed fma.rn.f32x2.
// Kernel 2: routing, cluster(2) per batch — R7-proven (61.9us), verbatim.

#define BB 512
#define RR 640
#define RHALF 320
#define CC 10
#define OO 16
#define COO 160
#define II 8

__device__ __half g_uhat[(size_t)BB * RR * COO];

typedef unsigned long long ull;
__device__ __forceinline__ ull pack2(float lo, float hi) {
    ull r; asm("mov.b64 %0, {%1, %2};" : "=l"(r) : "f"(lo), "f"(hi)); return r;
}
__device__ __forceinline__ void unpack2(ull v, float& lo, float& hi) {
    asm("mov.b64 {%0, %1}, %2;" : "=f"(lo), "=f"(hi) : "l"(v));
}
__device__ __forceinline__ ull fma2(ull a, ull b, ull c) {
    ull d; asm("fma.rn.f32x2 %0, %1, %2, %3;" : "=l"(d) : "l"(a), "l"(b), "l"(c)); return d;
}
__device__ __forceinline__ ull add2(ull a, ull b) {
    ull d; asm("add.rn.f32x2 %0, %1, %2;" : "=l"(d) : "l"(a), "l"(b)); return d;
}
__device__ __forceinline__ ull h2f2(unsigned int h) {
    __half2 hh = *reinterpret_cast<__half2*>(&h);
    float2 f = __half22float2(hh);
    ull u; memcpy(&u, &f, 8); return u;
}
__device__ __forceinline__ uint32_t smem_u32(const void* p) {
    uint32_t a;
    asm("{ .reg .u64 t; cvta.to.shared.u64 t, %1; cvt.u32.u64 %0, t; }" : "=r"(a) : "l"(p));
    return a;
}
__device__ __forceinline__ void dsmem_st_f32(uint32_t laddr, uint32_t rank, float v) {
    uint32_t raddr;
    asm volatile("mapa.shared::cluster.u32 %0, %1, %2;" : "=r"(raddr) : "r"(laddr), "r"(rank));
    asm volatile("st.shared::cluster.f32 [%0], %1;" :: "r"(raddr), "f"(v) : "memory");
}
#define CLUSTER_SYNC() do { \
    asm volatile("barrier.cluster.arrive.aligned;" ::: "memory"); \
    asm volatile("barrier.cluster.wait.aligned;"   ::: "memory"); } while (0)

// =====================================================================
// Kernel 1: grid=1280 (r = bid>>1, batch half = bid&1 -> 256 batches),
// 320 threads, 2 CTAs/SM, smem 13.3KB.
// thread: cg=t%40 -> co quad; pl=t/40 -> batch lane (step 8, 32 batches).
// Per batch: 2 LDS.128 (plain x) + 8 dup MOVs + 16 FFMA2 + 1 STG.64.
// =====================================================================
__global__ __launch_bounds__(320, 2) void uhat_kernel(const float* __restrict__ x,
                                                      const float* __restrict__ W) {
    const int r  = blockIdx.x >> 1;
    const int bh = blockIdx.x & 1;          // batch half: [bh*256, bh*256+256)
    __shared__ float  ws[COO * II];         // 5120B
    __shared__ float4 xs[256 * 2];          // 8192B: xs[bl*2+hf] = x[b][hf*4..]
    const int tid = threadIdx.x;

    for (int idx = tid; idx < COO * II; idx += 320)
        ws[idx] = W[(size_t)r * (COO * II) + idx];
    for (int idx = tid; idx < 256 * 2; idx += 320) {
        int bl = idx >> 1, hf = idx & 1;
        xs[idx] = *(const float4*)(x + (size_t)(bh * 256 + bl) * (RR * II) + r * II + hf * 4);
    }
    __syncthreads();

    const int cg = tid % 40;                // co quad base = cg*4
    const int pl = tid / 40;                // 0..7

    ull wp0[8], wp1[8];                     // co-pair packed W: 32 regs
#pragma unroll
    for (int i = 0; i < 8; i++) {
        wp0[i] = pack2(ws[(cg * 4 + 0) * 8 + i], ws[(cg * 4 + 1) * 8 + i]);
        wp1[i] = pack2(ws[(cg * 4 + 2) * 8 + i], ws[(cg * 4 + 3) * 8 + i]);
    }

    __half* outp = g_uhat;
    for (int bl = pl; bl < 256; bl += 8) {
        float4 xa = xs[bl * 2];
        float4 xb = xs[bl * 2 + 1];
        ull x0 = pack2(xa.x, xa.x), x1 = pack2(xa.y, xa.y);
        ull x2 = pack2(xa.z, xa.z), x3 = pack2(xa.w, xa.w);
        ull x4 = pack2(xb.x, xb.x), x5 = pack2(xb.y, xb.y);
        ull x6 = pack2(xb.z, xb.z), x7 = pack2(xb.w, xb.w);
        ull a0 = 0ull, a1 = 0ull;
        a0 = fma2(x0, wp0[0], a0);  a1 = fma2(x0, wp1[0], a1);
        a0 = fma2(x1, wp0[1], a0);  a1 = fma2(x1, wp1[1], a1);
        a0 = fma2(x2, wp0[2], a0);  a1 = fma2(x2, wp1[2], a1);
        a0 = fma2(x3, wp0[3], a0);  a1 = fma2(x3, wp1[3], a1);
        a0 = fma2(x4, wp0[4], a0);  a1 = fma2(x4, wp1[4], a1);
        a0 = fma2(x5, wp0[5], a0);  a1 = fma2(x5, wp1[5], a1);
        a0 = fma2(x6, wp0[6], a0);  a1 = fma2(x6, wp1[6], a1);
        a0 = fma2(x7, wp0[7], a0);  a1 = fma2(x7, wp1[7], a1);
        float f0, f1, f2, f3;
        unpack2(a0, f0, f1);
        unpack2(a1, f2, f3);
        __half2 h01 = __floats2half2_rn(f0, f1);
        __half2 h23 = __floats2half2_rn(f2, f3);
        uint2 st; st.x = *(unsigned*)&h01; st.y = *(unsigned*)&h23;
        const int bb = bh * 256 + bl;
        *(uint2*)(outp + ((size_t)bb * RR + r) * COO + cg * 4) = st;
    }
}

// =====================================================================
// Kernel 2 (R7-proven): routing, cluster(2) per batch. grid=1024, 320 thr,
// 114,688B smem, 2 CTAs/SM.
// SMEM per CTA:
//   [0,      102400) uh fp16 [r_local*160+co]   (320 r's)
//   [102400, 112640) UNION { redf f32[16][160] ; a_s/cij half[320*10] }
//   [112640, 113280) sv f32[160]
//   [113280, 114560) rbuf f32[2(par)][160]  (peer s partials)
// Mappings: thread-per-r (t = local r) for b_ij+softmax (merged phase);
// (rg=t/20 in [0,16), cq=t%20=c*2+oh) sweeps: 20 r's, uint4 per r.
// =====================================================================
#define SM_UNI   102400
#define SM_SV    112640
#define SM_RBUF  113280
#define SM_TOTAL 114688

__global__ __launch_bounds__(320, 2) __cluster_dims__(2, 1, 1)
void route_kernel(const float* __restrict__ bias, float* __restrict__ out) {
    extern __shared__ unsigned char sm[];
    __half* uh   = (__half*)(sm);
    float*  redf = (float*)(sm + SM_UNI);
    __half* a_s  = (__half*)(sm + SM_UNI);
    __half* cijh = (__half*)(sm + SM_UNI);
    float*  sv   = (float*)(sm + SM_SV);
    float*  rbuf = (float*)(sm + SM_RBUF);

    const int b  = blockIdx.x >> 1;
    const uint32_t rk = blockIdx.x & 1;       // ctarank in cluster
    const int t  = threadIdx.x;

    // ---- stage this CTA's half of u_hat[b] (100 KB fp16) ----
    {
        const uint4* src = (const uint4*)(g_uhat + ((size_t)b * RR + rk * RHALF) * COO);
        uint4* dst = (uint4*)uh;
#pragma unroll
        for (int i = 0; i < 20; i++)
            dst[i * 320 + t] = src[i * 320 + t];
    }

    const float biasv = (t < COO) ? bias[t] : 0.f;

    float bij[CC];
#pragma unroll
    for (int c = 0; c < CC; c++) bij[c] = 0.f;

    const int rg   = t / 20;                  // 16 groups of 20 local r's
    const int cq   = t % 20;                  // c*2 + ohalf
    const int c_of = cq >> 1;
    const int oh   = cq & 1;
    const __half* uptr0 = uh + (rg * 20) * COO + cq * 8;
    const uint32_t rbuf_base = smem_u32(rbuf);

    __syncthreads();

    // ---- iteration-0 fast path: c_ij = 0.1 folded into reduce ----
    {
        ull s0 = 0ull, s1 = 0ull, s2 = 0ull, s3 = 0ull;
        const __half* p = uptr0;
#pragma unroll 10
        for (int rr = 0; rr < 20; rr++) {
            uint4 h = *(const uint4*)p; p += COO;
            s0 = add2(s0, h2f2(h.x)); s1 = add2(s1, h2f2(h.y));
            s2 = add2(s2, h2f2(h.z)); s3 = add2(s3, h2f2(h.w));
        }
        float f0, f1, f2, f3, f4, f5, f6, f7;
        unpack2(s0, f0, f1); unpack2(s1, f2, f3);
        unpack2(s2, f4, f5); unpack2(s3, f6, f7);
        float* rp = redf + rg * COO + cq * 8;
        *(float4*)(rp)     = make_float4(f0, f1, f2, f3);
        *(float4*)(rp + 4) = make_float4(f4, f5, f6, f7);
    }
    __syncthreads();

    for (int it = 0; it < 3; ++it) {
        const int par = it & 1;
        // ---- local reduce + DSMEM exchange ----
        float s_loc = 0.f;
        if (t < COO) {
#pragma unroll
            for (int g = 0; g < 16; g++) s_loc += redf[g * COO + t];
            dsmem_st_f32(rbuf_base + (par * COO + t) * 4, 1u - rk, s_loc);
        }
        CLUSTER_SYNC();
        // ---- total s + squash (identical on both CTAs) ----
        if (t < COO) {
            float s = s_loc + rbuf[par * COO + t];
            s = (it == 0) ? fmaf(s, 0.1f, biasv) : (s + biasv);
            float n2 = s * s;
            n2 += __shfl_xor_sync(0xffffffffu, n2, 1);
            n2 += __shfl_xor_sync(0xffffffffu, n2, 2);
            n2 += __shfl_xor_sync(0xffffffffu, n2, 4);
            n2 += __shfl_xor_sync(0xffffffffu, n2, 8);
            float scale = sqrtf(n2) / (1.0f + n2 + 1e-8f);
            float v = s * scale;
            sv[t] = v;
            if (it == 2 && rk == 0) out[(size_t)b * COO + t] = v;
        }
        if (it == 2) break;
        __syncthreads();

        // ---- a_ij = <u_hat, v>; writes a_s (over redf, consumed above) ----
        {
            const float4 lv0 = *(const float4*)(sv + cq * 8);
            const float4 lv1 = *(const float4*)(sv + cq * 8 + 4);
            const ull v0 = pack2(lv0.x, lv0.y), v1 = pack2(lv0.z, lv0.w);
            const ull v2 = pack2(lv1.x, lv1.y), v3 = pack2(lv1.z, lv1.w);
            const __half* p = uptr0;
#pragma unroll 10
            for (int rr = 0; rr < 20; rr++) {
                uint4 h = *(const uint4*)p; p += COO;
                ull pp = fma2(h2f2(h.x), v0, 0ull);
                pp = fma2(h2f2(h.y), v1, pp);
                pp = fma2(h2f2(h.z), v2, pp);
                pp = fma2(h2f2(h.w), v3, pp);
                float plo, phi; unpack2(pp, plo, phi);
                float ps = plo + phi;
                ps += __shfl_xor_sync(0xffffffffu, ps, 1);
                if (oh == 0) a_s[(rg * 20 + rr) * CC + c_of] = __float2half_rn(ps);
            }
        }
        __syncthreads();

        // ---- merged: b_ij += a_ij, softmax -> cijh (same thread, same idx) ----
        {
            const __half2* ar = (const __half2*)(a_s + t * CC);
            float2 f[5];
#pragma unroll
            for (int q = 0; q < 5; q++) f[q] = __half22float2(ar[q]);
#pragma unroll
            for (int q = 0; q < 5; q++) {
                bij[2 * q]     += f[q].x;
                bij[2 * q + 1] += f[q].y;
            }
            float e[CC]; float ssum = 0.f;
#pragma unroll
            for (int c = 0; c < CC; c++) { e[c] = __expf(bij[c]); ssum += e[c]; }
            float inv = __fdividef(1.0f, ssum);
            __half2* cw = (__half2*)(cijh + t * CC);
#pragma unroll
            for (int q = 0; q < 5; q++)
                cw[q] = __floats2half2_rn(e[2 * q] * inv, e[2 * q + 1] * inv);
        }
        __syncthreads();

        // ---- s_j partials: sum_r c_ij * u_hat -> redf (bar before overlay) ----
        {
            ull s0 = 0ull, s1 = 0ull, s2 = 0ull, s3 = 0ull;
            const __half* cp = cijh + (rg * 20) * CC + c_of;
            const __half* p = uptr0;
#pragma unroll 10
            for (int rr = 0; rr < 20; rr++) {
                uint4 h = *(const uint4*)p; p += COO;
                float cwv = __half2float(*cp); cp += CC;
                ull cwp = pack2(cwv, cwv);
                s0 = fma2(h2f2(h.x), cwp, s0);
                s1 = fma2(h2f2(h.y), cwp, s1);
                s2 = fma2(h2f2(h.z), cwp, s2);
                s3 = fma2(h2f2(h.w), cwp, s3);
            }
            __syncthreads();   // all cij reads done before redf overlay write
            float f0, f1, f2, f3, f4, f5, f6, f7;
            unpack2(s0, f0, f1); unpack2(s1, f2, f3);
            unpack2(s2, f4, f5); unpack2(s3, f6, f7);
            float* rp = redf + rg * COO + cq * 8;
            *(float4*)(rp)     = make_float4(f0, f1, f2, f3);
            *(float4*)(rp + 4) = make_float4(f4, f5, f6, f7);
        }
        __syncthreads();
    }
}

// =====================================================================
extern "C" void kernel_launch(void* const* d_in, const int* in_sizes, int n_in,
                              void* d_out, int out_size) {
    const float* x = nullptr;
    const float* W = nullptr;
    const float* bias = nullptr;
    for (int i = 0; i < n_in; i++) {
        if (in_sizes[i] == BB * RR * II)            x    = (const float*)d_in[i];
        else if (in_sizes[i] == RR * CC * OO * II)  W    = (const float*)d_in[i];
        else if (in_sizes[i] == CC * OO)            bias = (const float*)d_in[i];
    }

    cudaFuncSetAttribute(route_kernel, cudaFuncAttributeMaxDynamicSharedMemorySize,
                         SM_TOTAL);

    uhat_kernel<<<RR * 2, 320>>>(x, W);
    route_kernel<<<BB * 2, 320, SM_TOTAL>>>(bias, (float*)d_out);
}